// round 2
// baseline (speedup 1.0000x reference)
#include <cuda_runtime.h>
#include <cuda_bf16.h>
#include <math.h>

// Problem constants
#define Bn   32
#define Sn   2048
#define En   512
#define Vn   32000
#define NGRP 16      // batch groups
#define CPG  8       // CTAs per group (column split of W_dec)
#define NCOL 64      // columns per CTA
#define NTHR 256
#define SQRT_E 22.627416997969522f
#define EPSLN 1e-6f

// ---------- static device scratch (no allocations allowed) ----------
__device__ float    g_u[2 * NGRP * 2 * En];        // double-buffered u exchange
__device__ float4   g_s[2 * NGRP * CPG];           // (s1_b0, s2_b0, s1_b1, s2_b1) per CTA
__device__ unsigned g_ctr[NGRP];                    // monotonic per-group arrival counters
__device__ float    g_logits[(size_t)Bn * Vn];     // 4.1 MB logits scratch

// ---------- sync helpers ----------
__device__ __forceinline__ unsigned ld_acquire_u32(const unsigned* p) {
    unsigned v;
    asm volatile("ld.acquire.gpu.global.u32 %0, [%1];" : "=r"(v) : "l"(p) : "memory");
    return v;
}
__device__ __forceinline__ void red_release_add(unsigned* p, unsigned v) {
    asm volatile("red.release.gpu.global.add.u32 [%0], %1;" :: "l"(p), "r"(v) : "memory");
}

// ===================== Kernel 1: recurrent scan =====================
// grid = 128 CTAs (16 groups x 8), 256 threads, ~145 KB dynamic smem.
// CTA (g, c) keeps W_dec[:, 64c : 64c+64) in smem and a full copy of the
// 2-batch state z (2x512). Per step: add embedding, matvec slice, exchange
// u-slices + moment partials through L2, layernorm, repeat.
__global__ void __launch_bounds__(NTHR, 1)
rnn_scan_kernel(const int* __restrict__ seq,
                const float* __restrict__ emb,
                const float* __restrict__ Wdec,
                const float* __restrict__ bdec,
                const float* __restrict__ gamma,
                const float* __restrict__ beta,
                float* __restrict__ outz)
{
    extern __shared__ float sm[];
    float* Ws   = sm;                 // 512*64 = 32768
    float* zs   = Ws + En * NCOL;     // 2*512
    float* gs   = zs + 2 * En;        // 512
    float* bs   = gs + En;            // 512
    float* bd   = bs + En;            // 512
    float* red  = bd + En;            // 8*16*8 = 1024
    float* s_sm = red + 1024;         // 4
    float* lnp  = s_sm + 4;           // 4  (mu0, rinv0, mu1, rinv1)

    const int tid = threadIdx.x;
    const int g   = blockIdx.x >> 3;
    const int c   = blockIdx.x & 7;

    // ---- init: load W slice, gamma/beta/b_dec, zero z ----
    {
        const float4* Wd4 = (const float4*)Wdec;
        float4* Ws4 = (float4*)Ws;
        #pragma unroll 4
        for (int n = tid; n < En * (NCOL / 4); n += NTHR) {
            int i = n >> 4, q = n & 15;               // row i, quad q within our 64 cols
            Ws4[n] = Wd4[i * (En / 4) + c * (NCOL / 4) + q];
        }
        for (int n = tid; n < En; n += NTHR) {
            gs[n] = gamma[n]; bs[n] = beta[n]; bd[n] = bdec[n];
        }
        for (int n = tid; n < 2 * En; n += NTHR) zs[n] = 0.f;
    }

    // per-thread fixed slot for emb-add / LN-apply phases (4 consecutive cols)
    const int be = tid >> 7;                 // batch within group (0/1)
    const int j4 = (tid << 2) & (En - 1);    // column base (0..508 step 4)
    const int brow = 2 * g + be;             // global batch row

    // matvec mapping
    const int jq = tid & 15;                 // quad of 4 columns within our 64
    const int h  = tid >> 4;                 // 16-way i-split, interleaved i = h + 16*ii

    __syncthreads();

    // prefetch embedding for t=0
    float4 epre;
    {
        int idx = __ldg(&seq[brow * Sn + 0]);
        epre = __ldg((const float4*)&emb[(size_t)idx * En + j4]);
    }

    for (int t = 0; t < Sn; ++t) {
        const int buf = t & 1;

        // ---- phase A: z += x_t (own slots); zero moment accumulators ----
        {
            float4 zc = *(float4*)&zs[be * En + j4];
            zc.x = fmaf(epre.x, SQRT_E, zc.x);
            zc.y = fmaf(epre.y, SQRT_E, zc.y);
            zc.z = fmaf(epre.z, SQRT_E, zc.z);
            zc.w = fmaf(epre.w, SQRT_E, zc.w);
            *(float4*)&zs[be * En + j4] = zc;
            if (tid < 4) s_sm[tid] = 0.f;
            if (t + 1 < Sn) {   // prefetch next step's embedding (hidden under matvec)
                int idx = __ldg(&seq[brow * Sn + (t + 1)]);
                epre = __ldg((const float4*)&emb[(size_t)idx * En + j4]);
            }
        }
        __syncthreads();   // B1

        // ---- phase B: matvec slice  mv[b][j] = sum_i z[b][i] * W[i][j] ----
        {
            float4 a0 = make_float4(0.f, 0.f, 0.f, 0.f);
            float4 a1 = make_float4(0.f, 0.f, 0.f, 0.f);
            const float* z0 = zs;
            const float* z1 = zs + En;
            #pragma unroll
            for (int ii = 0; ii < 32; ++ii) {
                int i = h + (ii << 4);
                float4 w = *(const float4*)&Ws[(i << 6) + (jq << 2)];
                float zz0 = z0[i], zz1 = z1[i];
                a0.x = fmaf(zz0, w.x, a0.x); a0.y = fmaf(zz0, w.y, a0.y);
                a0.z = fmaf(zz0, w.z, a0.z); a0.w = fmaf(zz0, w.w, a0.w);
                a1.x = fmaf(zz1, w.x, a1.x); a1.y = fmaf(zz1, w.y, a1.y);
                a1.z = fmaf(zz1, w.z, a1.z); a1.w = fmaf(zz1, w.w, a1.w);
            }
            // combine h-pairs within warp (lanes 0-15 keep the sum)
            a0.x += __shfl_down_sync(~0u, a0.x, 16); a0.y += __shfl_down_sync(~0u, a0.y, 16);
            a0.z += __shfl_down_sync(~0u, a0.z, 16); a0.w += __shfl_down_sync(~0u, a0.w, 16);
            a1.x += __shfl_down_sync(~0u, a1.x, 16); a1.y += __shfl_down_sync(~0u, a1.y, 16);
            a1.z += __shfl_down_sync(~0u, a1.z, 16); a1.w += __shfl_down_sync(~0u, a1.w, 16);
            if ((tid & 31) < 16) {
                float* r = &red[(tid >> 5) * 128 + jq * 8];
                r[0] = a0.x; r[1] = a0.y; r[2] = a0.z; r[3] = a0.w;
                r[4] = a1.x; r[5] = a1.y; r[6] = a1.z; r[7] = a1.w;
            }
        }
        __syncthreads();   // B2

        // ---- phase C: finish reduction, u = z_a + mv + b_dec, publish + moments ----
        if (tid < 128) {
            int b = tid >> 6, jl = tid & 63;
            int q2 = jl >> 2, k = jl & 3;
            float mv = 0.f;
            #pragma unroll
            for (int w = 0; w < 8; ++w) mv += red[w * 128 + q2 * 8 + b * 4 + k];
            int J = c * NCOL + jl;
            float u = zs[b * En + J] + mv + bd[J];
            g_u[(((buf * NGRP + g) * 2 + b) << 9) + J] = u;     // plain store; released below
            float s1 = u, s2 = u * u;
            #pragma unroll
            for (int off = 16; off; off >>= 1) {
                s1 += __shfl_xor_sync(~0u, s1, off);
                s2 += __shfl_xor_sync(~0u, s2, off);
            }
            if ((tid & 31) == 0) {
                atomicAdd(&s_sm[b * 2 + 0], s1);
                atomicAdd(&s_sm[b * 2 + 1], s2);
            }
        }
        __syncthreads();   // B3

        // ---- phase D/E: arrive (release) + spin for the whole group ----
        if (tid == 0) {
            float4 sv = make_float4(s_sm[0], s_sm[1], s_sm[2], s_sm[3]);
            g_s[(buf * NGRP + g) * CPG + c] = sv;
            red_release_add(&g_ctr[g], 1u);
            unsigned tgt = 8u * (unsigned)(t + 1);
            while (ld_acquire_u32(&g_ctr[g]) < tgt) { }
            // fold the 8 CTAs' moment partials
            float s10 = 0.f, s20 = 0.f, s11 = 0.f, s21 = 0.f;
            #pragma unroll
            for (int ci = 0; ci < CPG; ++ci) {
                float4 sv2 = __ldcg(&g_s[(buf * NGRP + g) * CPG + ci]);
                s10 += sv2.x; s20 += sv2.y; s11 += sv2.z; s21 += sv2.w;
            }
            float mu0 = s10 * (1.f / En);
            float va0 = (s20 - (float)En * mu0 * mu0) * (1.f / (En - 1));
            float mu1 = s11 * (1.f / En);
            float va1 = (s21 - (float)En * mu1 * mu1) * (1.f / (En - 1));
            lnp[0] = mu0; lnp[1] = 1.f / (sqrtf(va0) + EPSLN);
            lnp[2] = mu1; lnp[3] = 1.f / (sqrtf(va1) + EPSLN);
        }
        __syncthreads();   // B4

        // ---- phase G: gather full u row, apply layernorm into zs ----
        {
            float mu = lnp[be * 2 + 0], rv = lnp[be * 2 + 1];
            float4 uu = __ldcg((const float4*)&g_u[(((buf * NGRP + g) * 2 + be) << 9) + j4]);
            float4 gg = *(float4*)&gs[j4];
            float4 bb = *(float4*)&bs[j4];
            float4 zn;
            zn.x = fmaf(gg.x, (uu.x - mu) * rv, bb.x);
            zn.y = fmaf(gg.y, (uu.y - mu) * rv, bb.y);
            zn.z = fmaf(gg.z, (uu.z - mu) * rv, bb.z);
            zn.w = fmaf(gg.w, (uu.w - mu) * rv, bb.w);
            *(float4*)&zs[be * En + j4] = zn;
        }
        __syncthreads();   // B5 (zs consistent for next matvec)
    }

    // final z -> d_out (first B*E floats), CTA c==0 of each group writes
    if (c == 0) {
        *(float4*)&outz[brow * En + j4] = *(float4*)&zs[be * En + j4];
    }
}

// ===================== Kernel 2: logits = z @ W_voc + b_voc =====================
// grid = 250, block = 128; each thread owns one vocab column, all 32 batches in regs.
__global__ void __launch_bounds__(128)
vocab_gemm_kernel(const float* __restrict__ z,
                  const float* __restrict__ Wvoc,
                  const float* __restrict__ bvoc)
{
    extern __shared__ float zsh[];   // 32*512 floats = 64 KB
    for (int n = threadIdx.x; n < (Bn * En) / 4; n += 128)
        ((float4*)zsh)[n] = ((const float4*)z)[n];
    __syncthreads();

    const int v = blockIdx.x * 128 + threadIdx.x;
    float bias = __ldg(&bvoc[v]);
    float acc[Bn];
    #pragma unroll
    for (int b = 0; b < Bn; ++b) acc[b] = bias;

    for (int i = 0; i < En; i += 4) {
        float w0 = __ldg(&Wvoc[(size_t)(i + 0) * Vn + v]);
        float w1 = __ldg(&Wvoc[(size_t)(i + 1) * Vn + v]);
        float w2 = __ldg(&Wvoc[(size_t)(i + 2) * Vn + v]);
        float w3 = __ldg(&Wvoc[(size_t)(i + 3) * Vn + v]);
        #pragma unroll
        for (int b = 0; b < Bn; ++b) {
            float4 zz = *(const float4*)&zsh[b * En + i];
            acc[b] = fmaf(zz.x, w0, fmaf(zz.y, w1, fmaf(zz.z, w2, fmaf(zz.w, w3, acc[b]))));
        }
    }
    #pragma unroll
    for (int b = 0; b < Bn; ++b)
        g_logits[(size_t)b * Vn + v] = acc[b];
}

// ===================== Kernel 3: log_softmax + counter reset =====================
__global__ void __launch_bounds__(256)
logsoftmax_kernel(float* __restrict__ dout)
{
    __shared__ float sb[34];
    const int row = blockIdx.x;
    const int tid = threadIdx.x;
    if (row == 0 && tid < NGRP) g_ctr[tid] = 0u;   // reset for next replay

    const float* L = &g_logits[(size_t)row * Vn];

    // pass 1: max
    float m = -INFINITY;
    for (int v = tid; v < Vn; v += 256) m = fmaxf(m, __ldg(&L[v]));
    #pragma unroll
    for (int off = 16; off; off >>= 1) m = fmaxf(m, __shfl_xor_sync(~0u, m, off));
    if ((tid & 31) == 0) sb[tid >> 5] = m;
    __syncthreads();
    if (tid < 8) {
        float mm = sb[tid];
        #pragma unroll
        for (int off = 4; off; off >>= 1) mm = fmaxf(mm, __shfl_xor_sync(0xffu, mm, off));
        if (tid == 0) sb[32] = mm;
    }
    __syncthreads();
    const float M = sb[32];
    __syncthreads();

    // pass 2: sum exp
    float s = 0.f;
    for (int v = tid; v < Vn; v += 256) s += expf(__ldg(&L[v]) - M);
    #pragma unroll
    for (int off = 16; off; off >>= 1) s += __shfl_xor_sync(~0u, s, off);
    if ((tid & 31) == 0) sb[tid >> 5] = s;
    __syncthreads();
    if (tid < 8) {
        float ss = sb[tid];
        #pragma unroll
        for (int off = 4; off; off >>= 1) ss += __shfl_xor_sync(0xffu, ss, off);
        if (tid == 0) sb[33] = ss;
    }
    __syncthreads();
    const float lse = M + logf(sb[33]);

    // pass 3: write y
    float* Y = dout + Bn * En + (size_t)row * Vn;
    for (int v = tid; v < Vn; v += 256) Y[v] = __ldg(&L[v]) - lse;
}

// ===================== launch =====================
extern "C" void kernel_launch(void* const* d_in, const int* in_sizes, int n_in,
                              void* d_out, int out_size)
{
    // inputs (metadata order): hidden_state, output_sequence, emb_out,
    //                          W_dec, b_dec, gamma, beta, W_voc, b_voc
    const int*   seq   = (const int*)  d_in[1];
    const float* emb   = (const float*)d_in[2];
    const float* Wdec  = (const float*)d_in[3];
    const float* bdec  = (const float*)d_in[4];
    const float* gamma = (const float*)d_in[5];
    const float* beta  = (const float*)d_in[6];
    const float* Wvoc  = (const float*)d_in[7];
    const float* bvoc  = (const float*)d_in[8];
    float* out = (float*)d_out;

    const int smem1 = (En * NCOL + 2 * En + 3 * En + 1024 + 8) * (int)sizeof(float); // ~145.5 KB
    const int smem2 = Bn * En * (int)sizeof(float);                                   // 64 KB
    cudaFuncSetAttribute(rnn_scan_kernel,  cudaFuncAttributeMaxDynamicSharedMemorySize, smem1);
    cudaFuncSetAttribute(vocab_gemm_kernel, cudaFuncAttributeMaxDynamicSharedMemorySize, smem2);

    rnn_scan_kernel<<<NGRP * CPG, NTHR, smem1>>>(seq, emb, Wdec, bdec, gamma, beta, out);
    vocab_gemm_kernel<<<Vn / 128, 128, smem2>>>(out, Wvoc, bvoc);
    logsoftmax_kernel<<<Bn, 256>>>(out);
}